// round 4
// baseline (speedup 1.0000x reference)
#include <cuda_runtime.h>

constexpr int N_ = 50000;     // nodes
constexpr int E_ = 800000;    // edges
// LAGS=16, FILT=64, CIN=80 — H0==0 kills hidden channels; w_r/b_r dead.

__device__ float  g_deg_out[N_];
__device__ float  g_deg_in[N_];
__device__ __align__(16) float g_txo[N_ * 16];
__device__ __align__(16) float g_txi[N_ * 16];

__global__ void zero_kernel() {
    int i = blockIdx.x * blockDim.x + threadIdx.x;
    if (i < N_ * 16) { g_txo[i] = 0.f; g_txi[i] = 0.f; }
    if (i < N_)      { g_deg_out[i] = 0.f; g_deg_in[i] = 0.f; }
}

__global__ void degree_kernel(const int* __restrict__ ei,
                              const float* __restrict__ ew) {
    int e = blockIdx.x * blockDim.x + threadIdx.x;
    if (e >= E_) return;
    int r = ei[e];
    int c = ei[E_ + e];
    float w = ew[e];
    atomicAdd(&g_deg_out[r], w);
    atomicAdd(&g_deg_in[c], w);
}

__device__ __forceinline__ void red_add_v4(float* p, float a, float b, float c, float d) {
    asm volatile("red.global.add.v4.f32 [%0], {%1,%2,%3,%4};"
                 :: "l"(p), "f"(a), "f"(b), "f"(c), "f"(d) : "memory");
}

// One thread per edge, both directions: 1x index load pair, 8 LDG.128 gathers
// (L2-resident x), 8 RED.128 scatters. Atomic count is the floor: 25.6M f32 adds.
__global__ void scatter_kernel(const int* __restrict__ ei,
                               const float* __restrict__ x) {
    int e = blockIdx.x * blockDim.x + threadIdx.x;
    if (e >= E_) return;
    int r = ei[e];
    int c = ei[E_ + e];

    float d_o = g_deg_out[r]; d_o = (d_o > 0.f) ? d_o : 1.f;
    float d_i = g_deg_in[c];  d_i = (d_i > 0.f) ? d_i : 1.f;
    float so = 1.f / d_o;
    float si = 1.f / d_i;

    const float4* x4 = reinterpret_cast<const float4*>(x);
    float* po = &g_txo[c * 16];
    float* pi = &g_txi[r * 16];
#pragma unroll
    for (int q = 0; q < 4; q++) {
        float4 vr = x4[r * 4 + q];
        float4 vc = x4[c * 4 + q];
        red_add_v4(po + q * 4, so * vr.x, so * vr.y, so * vr.z, so * vr.w);
        red_add_v4(pi + q * 4, si * vc.x, si * vc.y, si * vc.z, si * vc.w);
    }
}

__device__ __forceinline__ unsigned long long pack2(float a, float b) {
    unsigned long long v;
    asm("mov.b64 %0, {%1,%2};" : "=l"(v) : "f"(a), "f"(b));
    return v;
}
__device__ __forceinline__ void unpack2(unsigned long long v, float& a, float& b) {
    asm("mov.b64 {%0,%1}, %2;" : "=f"(a), "=f"(b) : "l"(v));
}
__device__ __forceinline__ void fma2(unsigned long long& acc, unsigned long long a, unsigned long long b) {
    asm("fma.rn.f32x2 %0, %1, %2, %0;" : "+l"(acc) : "l"(a), "l"(b));
}

// Per-node fused epilogue, 4 threads per node (16 filters each).
//   F = [x, Tx_o, Tx_i] (48)
//   out = sum_j relu((1-sigmoid(F@Wz_j+bz_j)) * tanh(F@Wh_j+bh_j)) * lin_w_j + lin_b
// Weight smem layout per filter j: 24 groups of 16B {wz[2p],wz[2p+1],wh[2p],wh[2p+1]}
// -> one LDS.128 feeds two FFMA2 (az-pair + ah-pair).
__global__ void node_kernel(const float* __restrict__ x,
                            const float* __restrict__ w_z, const float* __restrict__ b_z,
                            const float* __restrict__ w_h, const float* __restrict__ b_h,
                            const float* __restrict__ lin_w, const float* __restrict__ lin_b,
                            float* __restrict__ out) {
    __shared__ __align__(16) float sW[64][96];   // [filter][interleaved z/h pairs]
    __shared__ float sBz[64];
    __shared__ float sBh[64];
    __shared__ float sLin[64];

    // w_* layout: (2, 2, 80, 64) -> ((d*2 + k)*80 + c)*64 + f
    const int PLANE = 80 * 64;
    for (int idx = threadIdx.x; idx < 48 * 64; idx += blockDim.x) {
        int f  = idx / 48;
        int ci = idx % 48;
        float vz, vh;
        if (ci < 16) {                       // hop 0: W[0,0]+W[1,0] (x rows)
            vz = w_z[0 * PLANE + ci * 64 + f] + w_z[2 * PLANE + ci * 64 + f];
            vh = w_h[0 * PLANE + ci * 64 + f] + w_h[2 * PLANE + ci * 64 + f];
        } else if (ci < 32) {                // Tx_o: W[0,1]
            int cc = ci - 16;
            vz = w_z[1 * PLANE + cc * 64 + f];
            vh = w_h[1 * PLANE + cc * 64 + f];
        } else {                             // Tx_i: W[1,1]
            int cc = ci - 32;
            vz = w_z[3 * PLANE + cc * 64 + f];
            vh = w_h[3 * PLANE + cc * 64 + f];
        }
        int p = ci >> 1;        // tap pair index 0..23
        int o = ci & 1;         // within pair
        sW[f][p * 4 + o]     = vz;   // slots {0,1} = wz pair
        sW[f][p * 4 + 2 + o] = vh;   // slots {2,3} = wh pair
    }
    if (threadIdx.x < 64) {
        sBz[threadIdx.x]  = b_z[threadIdx.x];
        sBh[threadIdx.x]  = b_h[threadIdx.x];
        sLin[threadIdx.x] = lin_w[threadIdx.x];
    }
    __syncthreads();

    int t = blockIdx.x * blockDim.x + threadIdx.x;
    int n = t >> 2;        // node
    int h = t & 3;         // filter slice 0..3
    if (n >= N_) return;

    // F vector as 24 packed f32x2 pairs (taps 2p, 2p+1)
    unsigned long long fvp[24];
    const float4* x4 = reinterpret_cast<const float4*>(x);
    const float4* o4 = reinterpret_cast<const float4*>(g_txo);
    const float4* i4 = reinterpret_cast<const float4*>(g_txi);
#pragma unroll
    for (int q = 0; q < 4; q++) {
        float4 v = x4[n * 4 + q];
        fvp[q * 2 + 0]      = pack2(v.x, v.y);
        fvp[q * 2 + 1]      = pack2(v.z, v.w);
        v = o4[n * 4 + q];
        fvp[8 + q * 2 + 0]  = pack2(v.x, v.y);
        fvp[8 + q * 2 + 1]  = pack2(v.z, v.w);
        v = i4[n * 4 + q];
        fvp[16 + q * 2 + 0] = pack2(v.x, v.y);
        fvp[16 + q * 2 + 1] = pack2(v.z, v.w);
    }

    const float LOG2E = 1.4426950408889634f;
    float acc = 0.f;
#pragma unroll 4
    for (int jj = 0; jj < 16; jj++) {
        int j = 4 * jj + h;   // 4 distinct bcast rows per warp, 384B apart
        const ulonglong2* w = reinterpret_cast<const ulonglong2*>(sW[j]);
        unsigned long long az2 = 0ull, ah2 = 0ull;
#pragma unroll
        for (int p = 0; p < 24; p++) {
            ulonglong2 v = w[p];          // LDS.128: (wz pair, wh pair)
            fma2(az2, v.x, fvp[p]);
            fma2(ah2, v.y, fvp[p]);
        }
        float a0, a1, az, ah;
        unpack2(az2, a0, a1); az = a0 + a1 + sBz[j];
        unpack2(ah2, a0, a1); ah = a0 + a1 + sBh[j];

        // (1 - sigmoid(az)) = 1/(1 + e^{az})
        float t0;
        asm("ex2.approx.f32 %0, %1;" : "=f"(t0) : "f"(az * LOG2E));
        float s;
        asm("rcp.approx.f32 %0, %1;" : "=f"(s) : "f"(1.f + t0));
        float ht;
        asm("tanh.approx.f32 %0, %1;" : "=f"(ht) : "f"(ah));
        float hv = fmaxf(s * ht, 0.f);
        acc = fmaf(hv, sLin[j], acc);
    }

    // combine the four filter-slices of this node (lanes 4n..4n+3 contiguous)
    acc += __shfl_xor_sync(0xffffffffu, acc, 1);
    acc += __shfl_xor_sync(0xffffffffu, acc, 2);
    if (h == 0) out[n] = acc + lin_b[0];
}

extern "C" void kernel_launch(void* const* d_in, const int* in_sizes, int n_in,
                              void* d_out, int out_size) {
    const float* x     = (const float*)d_in[0];
    const int*   ei    = (const int*)d_in[1];   // jnp.int64 materializes as int32 (x64 off)
    const float* ew    = (const float*)d_in[2];
    const float* w_z   = (const float*)d_in[3];
    const float* b_z   = (const float*)d_in[4];
    // d_in[5] = w_r, d_in[6] = b_r : dead (R gate multiplies H0 == 0)
    const float* w_h   = (const float*)d_in[7];
    const float* b_h   = (const float*)d_in[8];
    const float* lin_w = (const float*)d_in[9];
    const float* lin_b = (const float*)d_in[10];
    float*       out   = (float*)d_out;

    zero_kernel<<<(N_ * 16 + 255) / 256, 256>>>();
    degree_kernel<<<(E_ + 255) / 256, 256>>>(ei, ew);
    scatter_kernel<<<(E_ + 255) / 256, 256>>>(ei, x);
    node_kernel<<<(4 * N_ + 255) / 256, 256>>>(x, w_z, b_z, w_h, b_h, lin_w, lin_b, out);
}

// round 5
// speedup vs baseline: 1.8091x; 1.8091x over previous
#include <cuda_runtime.h>

constexpr int N_ = 50000;     // nodes
constexpr int E_ = 800000;    // edges
// LAGS=16, FILT=64, CIN=80 — H0==0 kills hidden channels; w_r/b_r dead.

__device__ float  g_deg_out[N_];
__device__ float  g_deg_in[N_];
__device__ __align__(16) float g_txo[N_ * 16];
__device__ __align__(16) float g_txi[N_ * 16];

__global__ void zero_kernel() {
    int i = blockIdx.x * blockDim.x + threadIdx.x;
    if (i < N_ * 16) { g_txo[i] = 0.f; g_txi[i] = 0.f; }
    if (i < N_)      { g_deg_out[i] = 0.f; g_deg_in[i] = 0.f; }
}

__global__ void degree_kernel(const int* __restrict__ ei,
                              const float* __restrict__ ew) {
    int e = blockIdx.x * blockDim.x + threadIdx.x;
    if (e >= E_) return;
    int r = ei[e];
    int c = ei[E_ + e];
    float w = ew[e];
    atomicAdd(&g_deg_out[r], w);
    atomicAdd(&g_deg_in[c], w);
}

__device__ __forceinline__ void red_add_v4(float* p, float a, float b, float c, float d) {
    asm volatile("red.global.add.v4.f32 [%0], {%1,%2,%3,%4};"
                 :: "l"(p), "f"(a), "f"(b), "f"(c), "f"(d) : "memory");
}

// One thread per edge, both directions: 1x index load pair, 8 LDG.128 gathers
// (L2-resident x), 8 RED.128 scatters. Atomic count is the floor: 6.4M RED.128.
__global__ void scatter_kernel(const int* __restrict__ ei,
                               const float* __restrict__ x) {
    int e = blockIdx.x * blockDim.x + threadIdx.x;
    if (e >= E_) return;
    int r = ei[e];
    int c = ei[E_ + e];

    float d_o = g_deg_out[r]; d_o = (d_o > 0.f) ? d_o : 1.f;
    float d_i = g_deg_in[c];  d_i = (d_i > 0.f) ? d_i : 1.f;
    float so = 1.f / d_o;
    float si = 1.f / d_i;

    const float4* x4 = reinterpret_cast<const float4*>(x);
    float* po = &g_txo[c * 16];
    float* pi = &g_txi[r * 16];
#pragma unroll
    for (int q = 0; q < 4; q++) {
        float4 vr = x4[r * 4 + q];
        float4 vc = x4[c * 4 + q];
        red_add_v4(po + q * 4, so * vr.x, so * vr.y, so * vr.z, so * vr.w);
        red_add_v4(pi + q * 4, si * vc.x, si * vc.y, si * vc.z, si * vc.w);
    }
}

__device__ __forceinline__ unsigned long long pack2(float a, float b) {
    unsigned long long v;
    asm("mov.b64 %0, {%1,%2};" : "=l"(v) : "f"(a), "f"(b));
    return v;
}
__device__ __forceinline__ void unpack2(unsigned long long v, float& a, float& b) {
    asm("mov.b64 {%0,%1}, %2;" : "=f"(a), "=f"(b) : "l"(v));
}
__device__ __forceinline__ void fma2(unsigned long long& acc, unsigned long long a, unsigned long long b) {
    asm("fma.rn.f32x2 %0, %1, %2, %0;" : "+l"(acc) : "l"(a), "l"(b));
}

// Per-node fused epilogue, 4 threads per node (16 filters each).
//   F = [x, Tx_o, Tx_i] (48)
//   out = sum_j relu((1-sigmoid(F@Wz_j+bz_j)) * tanh(F@Wh_j+bh_j)) * lin_w_j + lin_b
// Weight smem layout per filter j: 24 groups of 16B {wz[2p],wz[2p+1],wh[2p],wh[2p+1]}
// -> one LDS.128 feeds two FFMA2 (az-pair + ah-pair).
// ROW STRIDE = 100 floats (400B): 400 mod 128 = 16, so the warp's 4 broadcast
// rows (j = 4jj+h) sit at byte offsets {0,16,32,48} mod 128 — disjoint 16B
// windows -> conflict-free single-phase LDS.128 (the R4 96-float stride put
// all 4 rows on identical banks: 4-way conflict, 4.6x regression).
constexpr int WROW = 100;

__global__ void node_kernel(const float* __restrict__ x,
                            const float* __restrict__ w_z, const float* __restrict__ b_z,
                            const float* __restrict__ w_h, const float* __restrict__ b_h,
                            const float* __restrict__ lin_w, const float* __restrict__ lin_b,
                            float* __restrict__ out) {
    __shared__ __align__(16) float sW[64][WROW];  // 96 used, padded to 100
    __shared__ float sBz[64];
    __shared__ float sBh[64];
    __shared__ float sLin[64];

    // w_* layout: (2, 2, 80, 64) -> ((d*2 + k)*80 + c)*64 + f
    const int PLANE = 80 * 64;
    for (int idx = threadIdx.x; idx < 48 * 64; idx += blockDim.x) {
        int f  = idx / 48;
        int ci = idx % 48;
        float vz, vh;
        if (ci < 16) {                       // hop 0: W[0,0]+W[1,0] (x rows)
            vz = w_z[0 * PLANE + ci * 64 + f] + w_z[2 * PLANE + ci * 64 + f];
            vh = w_h[0 * PLANE + ci * 64 + f] + w_h[2 * PLANE + ci * 64 + f];
        } else if (ci < 32) {                // Tx_o: W[0,1]
            int cc = ci - 16;
            vz = w_z[1 * PLANE + cc * 64 + f];
            vh = w_h[1 * PLANE + cc * 64 + f];
        } else {                             // Tx_i: W[1,1]
            int cc = ci - 32;
            vz = w_z[3 * PLANE + cc * 64 + f];
            vh = w_h[3 * PLANE + cc * 64 + f];
        }
        int p = ci >> 1;        // tap pair index 0..23
        int o = ci & 1;         // within pair
        sW[f][p * 4 + o]     = vz;   // slots {0,1} = wz pair
        sW[f][p * 4 + 2 + o] = vh;   // slots {2,3} = wh pair
    }
    if (threadIdx.x < 64) {
        sBz[threadIdx.x]  = b_z[threadIdx.x];
        sBh[threadIdx.x]  = b_h[threadIdx.x];
        sLin[threadIdx.x] = lin_w[threadIdx.x];
    }
    __syncthreads();

    int t = blockIdx.x * blockDim.x + threadIdx.x;
    int n = t >> 2;        // node
    int h = t & 3;         // filter slice 0..3
    if (n >= N_) return;

    // F vector as 24 packed f32x2 pairs (taps 2p, 2p+1)
    unsigned long long fvp[24];
    const float4* x4 = reinterpret_cast<const float4*>(x);
    const float4* o4 = reinterpret_cast<const float4*>(g_txo);
    const float4* i4 = reinterpret_cast<const float4*>(g_txi);
#pragma unroll
    for (int q = 0; q < 4; q++) {
        float4 v = x4[n * 4 + q];
        fvp[q * 2 + 0]      = pack2(v.x, v.y);
        fvp[q * 2 + 1]      = pack2(v.z, v.w);
        v = o4[n * 4 + q];
        fvp[8 + q * 2 + 0]  = pack2(v.x, v.y);
        fvp[8 + q * 2 + 1]  = pack2(v.z, v.w);
        v = i4[n * 4 + q];
        fvp[16 + q * 2 + 0] = pack2(v.x, v.y);
        fvp[16 + q * 2 + 1] = pack2(v.z, v.w);
    }

    const float LOG2E = 1.4426950408889634f;
    float acc = 0.f;
#pragma unroll 4
    for (int jj = 0; jj < 16; jj++) {
        int j = 4 * jj + h;   // 4 distinct bcast rows, banks disjoint via WROW pad
        const ulonglong2* w = reinterpret_cast<const ulonglong2*>(&sW[j][0]);
        unsigned long long az2 = 0ull, ah2 = 0ull;
#pragma unroll
        for (int p = 0; p < 24; p++) {
            ulonglong2 v = w[p];          // LDS.128: (wz pair, wh pair)
            fma2(az2, v.x, fvp[p]);
            fma2(ah2, v.y, fvp[p]);
        }
        float a0, a1, az, ah;
        unpack2(az2, a0, a1); az = a0 + a1 + sBz[j];
        unpack2(ah2, a0, a1); ah = a0 + a1 + sBh[j];

        // (1 - sigmoid(az)) = 1/(1 + e^{az})
        float t0;
        asm("ex2.approx.f32 %0, %1;" : "=f"(t0) : "f"(az * LOG2E));
        float s;
        asm("rcp.approx.f32 %0, %1;" : "=f"(s) : "f"(1.f + t0));
        float ht;
        asm("tanh.approx.f32 %0, %1;" : "=f"(ht) : "f"(ah));
        float hv = fmaxf(s * ht, 0.f);
        acc = fmaf(hv, sLin[j], acc);
    }

    // combine the four filter-slices of this node (lanes 4n..4n+3 contiguous)
    acc += __shfl_xor_sync(0xffffffffu, acc, 1);
    acc += __shfl_xor_sync(0xffffffffu, acc, 2);
    if (h == 0) out[n] = acc + lin_b[0];
}

extern "C" void kernel_launch(void* const* d_in, const int* in_sizes, int n_in,
                              void* d_out, int out_size) {
    const float* x     = (const float*)d_in[0];
    const int*   ei    = (const int*)d_in[1];   // jnp.int64 materializes as int32 (x64 off)
    const float* ew    = (const float*)d_in[2];
    const float* w_z   = (const float*)d_in[3];
    const float* b_z   = (const float*)d_in[4];
    // d_in[5] = w_r, d_in[6] = b_r : dead (R gate multiplies H0 == 0)
    const float* w_h   = (const float*)d_in[7];
    const float* b_h   = (const float*)d_in[8];
    const float* lin_w = (const float*)d_in[9];
    const float* lin_b = (const float*)d_in[10];
    float*       out   = (float*)d_out;

    zero_kernel<<<(N_ * 16 + 255) / 256, 256>>>();
    degree_kernel<<<(E_ + 255) / 256, 256>>>(ei, ew);
    scatter_kernel<<<(E_ + 255) / 256, 256>>>(ei, x);
    node_kernel<<<(4 * N_ + 255) / 256, 256>>>(x, w_z, b_z, w_h, b_h, lin_w, lin_b, out);
}

// round 6
// speedup vs baseline: 2.4616x; 1.3607x over previous
#include <cuda_runtime.h>

constexpr int N_ = 50000;     // nodes
constexpr int E_ = 800000;    // edges
// LAGS=16, FILT=64, CIN=80 — H0==0 kills hidden channels; w_r/b_r dead.

__device__ float  g_deg_out[N_];
__device__ float  g_deg_in[N_];
__device__ __align__(16) float g_txo[N_ * 16];
__device__ __align__(16) float g_txi[N_ * 16];

__global__ void zero_kernel() {
    int i = blockIdx.x * blockDim.x + threadIdx.x;
    if (i < N_ * 16) { g_txo[i] = 0.f; g_txi[i] = 0.f; }
    if (i < N_)      { g_deg_out[i] = 0.f; g_deg_in[i] = 0.f; }
}

__global__ void degree_kernel(const int* __restrict__ ei,
                              const float* __restrict__ ew) {
    int e = blockIdx.x * blockDim.x + threadIdx.x;
    if (e >= E_) return;
    atomicAdd(&g_deg_out[ei[e]], ew[e]);
    atomicAdd(&g_deg_in[ei[E_ + e]], ew[e]);
}

__device__ __forceinline__ void red_add_v4(float* p, float a, float b, float c, float d) {
    asm volatile("red.global.add.v4.f32 [%0], {%1,%2,%3,%4};"
                 :: "l"(p), "f"(a), "f"(b), "f"(c), "f"(d) : "memory");
}

// One thread per edge, both directions: gather x rows (L2-hit), scale, 8x RED.128.
__global__ void scatter_kernel(const int* __restrict__ ei,
                               const float* __restrict__ x) {
    int e = blockIdx.x * blockDim.x + threadIdx.x;
    if (e >= E_) return;
    int r = ei[e];
    int c = ei[E_ + e];

    float d_o = g_deg_out[r]; d_o = (d_o > 0.f) ? d_o : 1.f;
    float d_i = g_deg_in[c];  d_i = (d_i > 0.f) ? d_i : 1.f;
    float so = 1.f / d_o;
    float si = 1.f / d_i;

    const float4* x4 = reinterpret_cast<const float4*>(x);
    float* po = &g_txo[c * 16];
    float* pi = &g_txi[r * 16];
#pragma unroll
    for (int q = 0; q < 4; q++) {
        float4 vr = x4[r * 4 + q];
        float4 vc = x4[c * 4 + q];
        red_add_v4(po + q * 4, so * vr.x, so * vr.y, so * vr.z, so * vr.w);
        red_add_v4(pi + q * 4, si * vc.x, si * vc.y, si * vc.z, si * vc.w);
    }
}

typedef unsigned long long ull;
__device__ __forceinline__ ull pack2(float a, float b) {
    ull v; asm("mov.b64 %0, {%1,%2};" : "=l"(v) : "f"(a), "f"(b)); return v;
}
__device__ __forceinline__ void unpack2(ull v, float& a, float& b) {
    asm("mov.b64 {%0,%1}, %2;" : "=f"(a), "=f"(b) : "l"(v));
}
__device__ __forceinline__ void fma2(ull& acc, ull a, ull b) {
    asm("fma.rn.f32x2 %0, %1, %2, %0;" : "+l"(acc) : "l"(a), "l"(b));
}

// Effective weight: hop-0 fold + block structure (48 live channels of 80).
// w layout: (2,2,80,64) -> ((d*2+k)*80+c)*64+f ; PLANE = 80*64.
__device__ __forceinline__ float weff(const float* __restrict__ w, int ci, int j) {
    const int PLANE = 80 * 64;
    if (ci < 16)  return w[ci * 64 + j] + w[2 * PLANE + ci * 64 + j]; // x rows
    if (ci < 32)  return w[1 * PLANE + (ci - 16) * 64 + j];           // Tx_o
    return w[3 * PLANE + (ci - 32) * 64 + j];                          // Tx_i
}

// Weights-in-registers node kernel.
// Block = 256 threads = 4 groups x 2 warps. Each warp owns 32 filters
// (1 per lane, all 48 taps in regs as 24 f32x2). Each group streams 32 nodes:
// feature reads are full-warp smem broadcasts (1 wavefront per LDS.64).
// Per node: warp computes 32 filters' relu((1-sig(z))*tanh(h))*lin, 5-shfl
// reduce, two warp-partials combined at the end.
constexpr int NT = 128;   // nodes per block

__global__ __launch_bounds__(256, 2)
void node_kernel(const float* __restrict__ x,
                 const float* __restrict__ w_z, const float* __restrict__ b_z,
                 const float* __restrict__ w_h, const float* __restrict__ b_h,
                 const float* __restrict__ lin_w, const float* __restrict__ lin_b,
                 float* __restrict__ out) {
    __shared__ __align__(16) float sF[NT][48];   // [node][channel]
    __shared__ float sPart[2][NT];

    int tid  = threadIdx.x;
    int lane = tid & 31;
    int wp   = (tid >> 5) & 1;        // which 32-filter half
    int grp  = tid >> 6;              // node sub-group 0..3
    int j    = wp * 32 + lane;        // my filter

    // ---- weights into registers (one-time; gmem reads are coalesced over j)
    ull wz2[24], wh2[24];
#pragma unroll
    for (int p = 0; p < 24; p++) {
        wz2[p] = pack2(weff(w_z, 2 * p, j), weff(w_z, 2 * p + 1, j));
        wh2[p] = pack2(weff(w_h, 2 * p, j), weff(w_h, 2 * p + 1, j));
    }
    float bz = b_z[j], bh = b_h[j], lw = lin_w[j];
    float lb = lin_b[0];

    // ---- stage this block's node features (x | txo | txi) into smem
    int base = blockIdx.x * NT;
    const float4* x4 = reinterpret_cast<const float4*>(x);
    const float4* o4 = reinterpret_cast<const float4*>(g_txo);
    const float4* i4 = reinterpret_cast<const float4*>(g_txi);
    for (int idx = tid; idx < NT * 12; idx += 256) {
        int nl = idx / 12;
        int q  = idx % 12;
        int n  = base + nl;
        float4 v = make_float4(0.f, 0.f, 0.f, 0.f);
        if (n < N_) {
            if (q < 4)      v = x4[n * 4 + q];
            else if (q < 8) v = o4[n * 4 + (q - 4)];
            else            v = i4[n * 4 + (q - 8)];
        }
        *reinterpret_cast<float4*>(&sF[nl][q * 4]) = v;
    }
    __syncthreads();

    const float LOG2E = 1.4426950408889634f;
    for (int i = 0; i < 32; i++) {
        int nl = (grp << 5) + i;
        if (base + nl >= N_) break;   // group-uniform branch
        const ull* f = reinterpret_cast<const ull*>(&sF[nl][0]);

        ull a0 = 0ull, a1 = 0ull, h0 = 0ull, h1 = 0ull;
#pragma unroll
        for (int p = 0; p < 24; p += 2) {
            ull f0 = f[p], f1 = f[p + 1];        // broadcast LDS.64
            fma2(a0, wz2[p], f0);
            fma2(h0, wh2[p], f0);
            fma2(a1, wz2[p + 1], f1);
            fma2(h1, wh2[p + 1], f1);
        }
        float s0, s1, s2, s3;
        unpack2(a0, s0, s1); unpack2(a1, s2, s3);
        float az = (s0 + s2) + (s1 + s3) + bz;
        unpack2(h0, s0, s1); unpack2(h1, s2, s3);
        float ah = (s0 + s2) + (s1 + s3) + bh;

        float e;  asm("ex2.approx.f32 %0, %1;" : "=f"(e) : "f"(az * LOG2E));
        float sg; asm("rcp.approx.f32 %0, %1;" : "=f"(sg) : "f"(1.f + e)); // 1-sigmoid
        float ht; asm("tanh.approx.f32 %0, %1;" : "=f"(ht) : "f"(ah));
        float c = fmaxf(sg * ht, 0.f) * lw;

        c += __shfl_xor_sync(0xffffffffu, c, 16);
        c += __shfl_xor_sync(0xffffffffu, c, 8);
        c += __shfl_xor_sync(0xffffffffu, c, 4);
        c += __shfl_xor_sync(0xffffffffu, c, 2);
        c += __shfl_xor_sync(0xffffffffu, c, 1);
        if (lane == 0) sPart[wp][nl] = c;
    }
    __syncthreads();

    if (tid < NT) {
        int n = base + tid;
        if (n < N_) out[n] = sPart[0][tid] + sPart[1][tid] + lb;
    }
}

extern "C" void kernel_launch(void* const* d_in, const int* in_sizes, int n_in,
                              void* d_out, int out_size) {
    const float* x     = (const float*)d_in[0];
    const int*   ei    = (const int*)d_in[1];   // jnp.int64 materializes as int32
    const float* ew    = (const float*)d_in[2];
    const float* w_z   = (const float*)d_in[3];
    const float* b_z   = (const float*)d_in[4];
    // d_in[5] = w_r, d_in[6] = b_r : dead (R gate multiplies H0 == 0)
    const float* w_h   = (const float*)d_in[7];
    const float* b_h   = (const float*)d_in[8];
    const float* lin_w = (const float*)d_in[9];
    const float* lin_b = (const float*)d_in[10];
    float*       out   = (float*)d_out;

    zero_kernel<<<(N_ * 16 + 255) / 256, 256>>>();
    degree_kernel<<<(E_ + 255) / 256, 256>>>(ei, ew);
    scatter_kernel<<<(E_ + 255) / 256, 256>>>(ei, x);
    node_kernel<<<(N_ + NT - 1) / NT, 256>>>(x, w_z, b_z, w_h, b_h, lin_w, lin_b, out);
}